// round 4
// baseline (speedup 1.0000x reference)
#include <cuda_runtime.h>
#include <cstdint>

#define CC   3
#define OO   8
#define HH   128
#define WW   128
#define HO   124
#define WO   124
#define P25  25

#define TILE_W 32
#define XT_W   36      // staged input cols (32 + 4 halo)
#define SROW   72      // splatted floats per staged row (2 * XT_W)
#define XT_H   46      // staged rows (42-row tile + 4 halo)

// Packed fp32x2 add: one FADD2 computes (x + khn, x + kmn) for hit & miss.
__device__ __forceinline__ void fadd2(unsigned long long a, unsigned long long b,
                                      float& lo, float& hi)
{
    asm("{\n\t.reg .b64 t;\n\tadd.rn.f32x2 t, %2, %3;\n\tmov.b64 {%0, %1}, t;\n\t}"
        : "=f"(lo), "=f"(hi) : "l"(a), "l"(b));
}

// One output row from a 6-slot ring. Uses slots (BASE+u)%6, u=0..4.
// All indices compile-time -> arrays stay in registers.
template<int BASE>
__device__ __forceinline__ float2 row_compute6(const unsigned long long* __restrict__ w,
                                               const unsigned long long* __restrict__ kp)
{
    float hu[5], mu[5];
#pragma unroll
    for (int u = 0; u < 5; ++u) {
        const int s = ((BASE + u) % 6) * 5;
        fadd2(w[s], kp[u * 5], hu[u], mu[u]);
#pragma unroll
        for (int v = 1; v < 5; ++v) {
            float lo, hi;
            fadd2(w[s + v], kp[u * 5 + v], lo, hi);
            hu[u] = fminf(hu[u], lo);
            mu[u] = fmaxf(mu[u], hi);
        }
    }
    const float hit = fminf(fminf(fminf(hu[0], hu[1]), fminf(hu[2], hu[3])), hu[4]);
    const float mis = fmaxf(fmaxf(fmaxf(mu[0], mu[1]), fmaxf(mu[2], mu[3])), mu[4]);
    return make_float2(hit, mis);
}

// One step: load x rows (rbase+J+4, rbase+J+5) into ring slots, then compute
// output rows (rbase+J) and (rbase+J+1). J in {0,2,4}; ring slot = row % 6.
#define ROW_STEP2(J)                                                             \
    do {                                                                         \
        const float* nr0 = sx2 + (rbase + (J) + 4) * SROW + 2 * tx;              \
        const float* nr1 = nr0 + SROW;                                           \
        _Pragma("unroll")                                                        \
        for (int v = 0; v < 5; ++v) {                                            \
            w[(((J) + 4) % 6) * 5 + v] =                                         \
                *(const unsigned long long*)(nr0 + 2 * v);                       \
            w[(((J) + 5) % 6) * 5 + v] =                                         \
                *(const unsigned long long*)(nr1 + 2 * v);                       \
        }                                                                        \
        const float2 a = row_compute6<(J)>(w, kp);                               \
        const float2 b2 = row_compute6<(J) + 1>(w, kp);                          \
        if (colok && (hbase + (J)) < HO)     op[0]  = a.x - a.y;                 \
        if (colok && (hbase + (J) + 1) < HO) op[WO] = b2.x - b2.y;               \
        op += 2 * WO;                                                            \
    } while (0)

__global__ __launch_bounds__(256, 2)
void mnn_kernel(const float* __restrict__ x,
                const float* __restrict__ kh_g,
                const float* __restrict__ km_g,
                float* __restrict__ out)
{
    __shared__ float sx2[XT_H * SROW];   // splatted tile: 46 x 72 floats

    const int tx  = threadIdx.x;          // 0..31  output column in tile
    const int o   = threadIdx.y;          // 0..7   output channel
    const int wo0 = blockIdx.x * TILE_W;
    const int ho0 = blockIdx.y * 42;      // y-tiles at rows 0, 42, 84
    const int bc  = blockIdx.z;           // b*C + c
    const int b   = bc / CC;
    const int c   = bc % CC;
    const int tid = o * 32 + tx;

    // ---- stage x tile into shared, pre-splatted: sx2[r][2j]=sx2[r][2j+1]=x ----
    const float* __restrict__ xb = x + (size_t)bc * HH * WW;
    for (int i = tid; i < XT_H * XT_W; i += 256) {
        const int rr  = i / XT_W;
        const int cc2 = i % XT_W;
        const int gr  = ho0 + rr;
        const int gc  = wo0 + cc2;
        const float v = (gr < HH && gc < WW) ? xb[gr * WW + gc] : 0.0f;
        *(float2*)&sx2[rr * SROW + 2 * cc2] = make_float2(v, v);
    }

    // ---- weights packed as (-K_hit, -K_miss) 64-bit pairs ----
    unsigned long long kp[P25];
    {
        const float* __restrict__ khp = kh_g + (size_t)(o * CC + c) * P25;
        const float* __restrict__ kmp = km_g + (size_t)(o * CC + c) * P25;
#pragma unroll
        for (int p = 0; p < P25; ++p) {
            const float a  = -__ldg(khp + p);
            const float b2 = -__ldg(kmp + p);
            asm("mov.b64 %0, {%1, %2};" : "=l"(kp[p]) : "f"(a), "f"(b2));
        }
    }
    __syncthreads();

    // ---- ring prologue: local x rows 0..3 into slots 0..3 ----
    unsigned long long w[30];             // 6-row ring, 5 pairs per row
#pragma unroll
    for (int i = 0; i < 4; ++i)
#pragma unroll
        for (int v = 0; v < 5; ++v)
            w[i * 5 + v] =
                *(const unsigned long long*)(sx2 + i * SROW + 2 * (tx + v));

    const bool colok = (wo0 + tx) < WO;
    float* __restrict__ op =
        out + ((size_t)(b * OO * CC + o * CC + c)) * HO * WO
            + (size_t)ho0 * WO + wo0 + tx;

    // ---- 7 groups x 3 steps x 2 rows = 42 output rows ----
    int rbase = 0;
    for (int g = 0; g < 7; ++g) {
        const int hbase = ho0 + rbase;
        ROW_STEP2(0);
        ROW_STEP2(2);
        ROW_STEP2(4);
        rbase += 6;
    }
}

extern "C" void kernel_launch(void* const* d_in, const int* in_sizes, int n_in,
                              void* d_out, int out_size)
{
    const float* x     = (const float*)d_in[0];
    const float* K_hit = (const float*)d_in[1];
    const float* K_mis = (const float*)d_in[2];
    float* out = (float*)d_out;

    dim3 grid(4, 3, OO * CC);   // 288 blocks, 2/SM, ~single wave
    dim3 block(32, 8);
    mnn_kernel<<<grid, block>>>(x, K_hit, K_mis, out);
}